// round 3
// baseline (speedup 1.0000x reference)
#include <cuda_runtime.h>

#define BB 8
#define CC 32
#define FF 8
#define HH 128
#define WW 128
#define IHP 129
#define IWP 132                       // padded row stride (floats), 528 B (16B-aligned)
#define NW 8                          // 256 threads
#define DSTR 132
#define SMEM_FLOATS (IHP*IWP + NW*DSTR)   // 17028 + 1056 = 18084 -> 72336 B

// ---------------------------------------------------------------------------
// Fused kernel: block = (h-quarter, bc). Builds padded integral image in smem
// (duplicated per quarter), then warp f computes 32 output rows with a rolling
// register window over integral rows.
// ---------------------------------------------------------------------------
__global__ void __launch_bounds__(256) boxconv_fused(
    const float* __restrict__ in,
    const float* __restrict__ xmn, const float* __restrict__ xmx,
    const float* __restrict__ ymn, const float* __restrict__ ymx,
    float* __restrict__ out)
{
    extern __shared__ float sm[];
    float* I = sm;                                  // [IHP][IWP]

    const int bc   = blockIdx.y;                    // b*C + c
    const int quarter = blockIdx.x;                 // h in [32q, 32q+32)
    const int tid  = threadIdx.x;
    const int wid  = tid >> 5;
    const int lane = tid & 31;

    // ---- Phase A: row exclusive-scan, float4 per lane --------------------
    if (tid < IWP) I[tid] = 0.0f;                   // row 0 = 0

    const float* img = in + (size_t)bc * (HH * WW);
#pragma unroll
    for (int r = 0; r < HH / NW; ++r) {
        int row = wid * (HH / NW) + r;              // 0..127
        float4 c = *(const float4*)(img + (size_t)row * WW + 4 * lane);
        float s4 = c.x + c.y + c.z + c.w;
        float x = __shfl_up_sync(0xffffffffu, s4, 1);
        if (lane == 0) x = 0.0f;
#pragma unroll
        for (int off = 1; off < 32; off <<= 1) {
            float t = __shfl_up_sync(0xffffffffu, x, off);
            if (lane >= off) x += t;
        }
        // x = exclusive prefix of lane sums
        float4 o;
        o.x = x;
        o.y = x + c.x;
        o.z = o.y + c.y;
        o.w = o.z + c.z;
        float* dst = I + (size_t)(row + 1) * IWP;
        *(float4*)(dst + 4 * lane) = o;             // cols 0..127 (exclusive)
        if (lane == 31) dst[128] = o.w + c.w;       // col 128 = row total
    }
    __syncthreads();

    // ---- Phase B: column accumulate, float4 per thread -------------------
    if (tid < 33) {                                 // cols 4t..4t+3 (129..131 padding, harmless)
        float* col = I + 4 * tid;
        float4 s = make_float4(0.f, 0.f, 0.f, 0.f);
#pragma unroll 4
        for (int i = 1; i <= 128; ++i) {
            float4 v = *(float4*)(col + (size_t)i * IWP);
            s.x += v.x; s.y += v.y; s.z += v.z; s.w += v.w;
            *(float4*)(col + (size_t)i * IWP) = s;
        }
    }
    __syncthreads();

    // ---- Phase C: warp = f, 32 h rows, rolling register window -----------
    const int f  = wid;
    const int cf = (bc % CC) * FF + f;
    const float Hf = 128.0f, Wf = 128.0f;

    const float xm = __ldg(&xmn[cf]) * Hf;
    const float xM = __ldg(&xmx[cf]) * Hf;
    const float ym = __ldg(&ymn[cf]) * Wf;
    const float yM = __ldg(&ymx[cf]) * Wf;

    // Column-interp params: h-invariant, once per lane.
    int   j0[4], j1[4];
    float b0[4], b1[4];
#pragma unroll
    for (int k = 0; k < 4; ++k) {
        float wv = (float)(lane + 32 * k);
        float v0 = fminf(fmaxf(wv + ym, 0.0f), Wf);
        float v1 = fminf(fmaxf(wv + yM + 1.0f, 0.0f), Wf);
        float j0f = fminf(floorf(v0), Wf - 1.0f);
        float j1f = fminf(floorf(v1), Wf - 1.0f);
        b0[k] = v0 - j0f;
        b1[k] = v1 - j1f;
        j0[k] = (int)j0f;
        j1[k] = (int)j1f;
    }

    float* D = sm + IHP * IWP + wid * DSTR;
    float* outBase = out + ((size_t)(bc * FF + f) * HH) * WW;
    const int h0 = quarter * 32;

    float4 p0, q0, p1, q1;                          // rows i0, i0+1, i1, i1+1
    float e00 = 0.f, e01 = 0.f, e10 = 0.f, e11 = 0.f; // their col-128 values
    int pi0 = -2, pi1 = -2;

    for (int hh = 0; hh < 32; ++hh) {
        const int h = h0 + hh;

        float u0 = fminf(fmaxf((float)h + xm, 0.0f), Hf);
        float u1 = fminf(fmaxf((float)h + xM + 1.0f, 0.0f), Hf);
        float i0f = fminf(floorf(u0), Hf - 1.0f);
        float i1f = fminf(floorf(u1), Hf - 1.0f);
        float a0 = u0 - i0f;
        float a1 = u1 - i1f;
        int i0 = (int)i0f;
        int i1 = (int)i1f;

        // Rolling update (branches are warp-uniform).
        if (i0 != pi0) {
            const float* base = I + (size_t)i0 * IWP;
            if (i0 == pi0 + 1) { p0 = q0; e00 = e01; }
            else { p0 = *(const float4*)(base + 4 * lane); e00 = base[128]; }
            q0 = *(const float4*)(base + IWP + 4 * lane); e01 = base[IWP + 128];
            pi0 = i0;
        }
        if (i1 != pi1) {
            const float* base = I + (size_t)i1 * IWP;
            if (i1 == pi1 + 1) { p1 = q1; e10 = e11; }
            else { p1 = *(const float4*)(base + 4 * lane); e10 = base[128]; }
            q1 = *(const float4*)(base + IWP + 4 * lane); e11 = base[IWP + 128];
            pi1 = i1;
        }

        // D = rowlerp(i1,a1) - rowlerp(i0,a0)
        float4 d;
        d.x = (p1.x + a1 * (q1.x - p1.x)) - (p0.x + a0 * (q0.x - p0.x));
        d.y = (p1.y + a1 * (q1.y - p1.y)) - (p0.y + a0 * (q0.y - p0.y));
        d.z = (p1.z + a1 * (q1.z - p1.z)) - (p0.z + a0 * (q0.z - p0.z));
        d.w = (p1.w + a1 * (q1.w - p1.w)) - (p0.w + a0 * (q0.w - p0.w));
        *(float4*)(D + 4 * lane) = d;
        if (lane == 0)
            D[128] = (e10 + a1 * (e11 - e10)) - (e00 + a0 * (e01 - e00));
        __syncwarp();

        float* orow = outBase + (size_t)h * WW + lane;
#pragma unroll
        for (int k = 0; k < 4; ++k) {
            float d00 = D[j0[k]], d01 = D[j0[k] + 1];
            float d10 = D[j1[k]], d11 = D[j1[k] + 1];
            orow[32 * k] = (d10 + b1[k] * (d11 - d10))
                         - (d00 + b0[k] * (d01 - d00));
        }
        __syncwarp();   // protect D before next overwrite
    }
}

// ---------------------------------------------------------------------------
extern "C" void kernel_launch(void* const* d_in, const int* in_sizes, int n_in,
                              void* d_out, int out_size) {
    const float* input = (const float*)d_in[0];
    const float* x_min = (const float*)d_in[1];
    const float* x_max = (const float*)d_in[2];
    const float* y_min = (const float*)d_in[3];
    const float* y_max = (const float*)d_in[4];
    float* out = (float*)d_out;

    static int configured = 0;
    const int smem_bytes = SMEM_FLOATS * sizeof(float);   // 72336 B
    if (!configured) {
        cudaFuncSetAttribute(boxconv_fused,
                             cudaFuncAttributeMaxDynamicSharedMemorySize,
                             smem_bytes);
        configured = 1;
    }

    dim3 grid(4, BB * CC);    // (h-quarter, bc)
    boxconv_fused<<<grid, 256, smem_bytes>>>(
        input, x_min, x_max, y_min, y_max, out);
}